// round 11
// baseline (speedup 1.0000x reference)
#include <cuda_runtime.h>
#include <cuda_bf16.h>
#include <cstdint>

#define N_NODES 50000
#define N_EDGES 1250000
#define HID 64
#define CDIM 128
#define NTILE 32                                     // K1 GEMM tile
#define N_TILES ((N_NODES + NTILE - 1) / NTILE)
#define SCAT_BLOCKS 444
#define GEMM_BLOCKS 148
#define TOTAL_BLOCKS (SCAT_BLOCKS + GEMM_BLOCKS)
#define TOTAL_ITEMS (16LL * N_EDGES)
#define SPLIT_ITEMS 17500000LL

#define MT 128                                       // mlp2 nodes per block
#define M_BLOCKS ((N_NODES + MT - 1) / MT)           // 391
#define A_PAD 76          // act row pad (words)
#define WL_STRIDE 20      // per-lane words in frag-layout weights (bank-disjoint)
#define W_KT_BLK (32 * WL_STRIDE)                    // 640 words per kt tile
#define W_WORDS (8 * W_KT_BLK)                       // 5120 words per weight mat

// scratch: t1 = x @ W1[0:64] + b1  (fp32, computed free inside K1)
__device__ float d_t1[(size_t)N_NODES * HID];

// ---------------------------------------------------------------------------
// helpers
// ---------------------------------------------------------------------------
__device__ __forceinline__ uint32_t f2tf32(float f) {
    uint32_t r; asm("cvt.rna.tf32.f32 %0, %1;" : "=r"(r) : "f"(f)); return r;
}

__device__ __forceinline__ void mma_tf32(float& d0, float& d1, float& d2, float& d3,
                                         uint32_t a0, uint32_t a1, uint32_t a2, uint32_t a3,
                                         uint32_t b0, uint32_t b1) {
    asm("mma.sync.aligned.m16n8k8.row.col.f32.tf32.tf32.f32 "
        "{%0,%1,%2,%3}, {%4,%5,%6,%7}, {%8,%9}, {%0,%1,%2,%3};"
        : "+f"(d0), "+f"(d1), "+f"(d2), "+f"(d3)
        : "r"(a0), "r"(a1), "r"(a2), "r"(a3), "r"(b0), "r"(b1));
}

// ---------------------------------------------------------------------------
// scatter: sequential edge_attr stream + v4 reductions (R7, proven)
// ---------------------------------------------------------------------------
__device__ __forceinline__ void scatter_range(const int* __restrict__ row,
                                              const float4* __restrict__ attr4,
                                              float* __restrict__ combined,
                                              long long beg, long long end,
                                              long long idx0, long long stride) {
    int lane = threadIdx.x & 31;
    int g = (int)((beg + idx0) & 15);
    long long idx = beg + idx0;

    while (idx - lane + 31 < end) {
        int e = (int)(idx >> 4);
        int r;
        if ((lane & 15) == 0) r = __ldg(row + e);
        r = __shfl_sync(0xffffffffu, r, lane & 16);
        float4 v = __ldg(attr4 + idx);
        float* dst = combined + (size_t)r * CDIM + HID + g * 4;
        asm volatile("red.global.add.v4.f32 [%0], {%1, %2, %3, %4};"
                     :: "l"(dst), "f"(v.x), "f"(v.y), "f"(v.z), "f"(v.w)
                     : "memory");
        idx += stride;
    }
    if (idx < end) {
        int e = (int)(idx >> 4);
        int r = __ldg(row + e);
        float4 v = __ldg(attr4 + idx);
        float* dst = combined + (size_t)r * CDIM + HID + g * 4;
        asm volatile("red.global.add.v4.f32 [%0], {%1, %2, %3, %4};"
                     :: "l"(dst), "f"(v.x), "f"(v.y), "f"(v.z), "f"(v.w)
                     : "memory");
    }
}

// ---------------------------------------------------------------------------
// K1: fused scatter + t1-GEMM (+ combined[:,0:64] = x copy)  (R7, proven)
// ---------------------------------------------------------------------------
__global__ void scatter_gemm_kernel(const int* __restrict__ row,
                                    const float4* __restrict__ attr4,
                                    const float4* __restrict__ x4,
                                    const float* __restrict__ W1,
                                    const float* __restrict__ b1,
                                    float* __restrict__ combined) {
    int tid = threadIdx.x;

    if (blockIdx.x < SCAT_BLOCKS) {
        long long idx0 = (long long)blockIdx.x * 256 + tid;
        scatter_range(row, attr4, combined, 0, SPLIT_ITEMS,
                      idx0, (long long)SCAT_BLOCKS * 256);
        return;
    }

    extern __shared__ float4 smem4[];
    float*  sW  = (float*)smem4;
    float4* sx4 = smem4 + (HID * HID) / 4;

    for (int i = tid; i < HID * HID; i += 256) sW[i] = W1[i];
    float bj = __ldg(b1 + (tid & 63));
    __syncthreads();

    int g = tid >> 6;
    int j = tid & 63;
    int bid = blockIdx.x - SCAT_BLOCKS;
    float4* comb4 = (float4*)combined;

    for (int tile = bid; tile < N_TILES; tile += GEMM_BLOCKS) {
        int node0 = tile * NTILE;
        for (int i = tid; i < NTILE * 16; i += 256) {
            int n = node0 + (i >> 4), q = i & 15;
            float4 v = make_float4(0.f, 0.f, 0.f, 0.f);
            if (n < N_NODES) {
                v = __ldg(x4 + (size_t)n * 16 + q);
                comb4[(size_t)n * 32 + q] = v;
            }
            sx4[i] = v;
        }
        __syncthreads();

        float acc[8];
        #pragma unroll
        for (int n = 0; n < 8; n++) acc[n] = bj;

        const float4* c0 = sx4 + g * 8 * 16;
        #pragma unroll 4
        for (int i4 = 0; i4 < 16; i4++) {
            float w0 = sW[(i4 * 4 + 0) * HID + j];
            float w1 = sW[(i4 * 4 + 1) * HID + j];
            float w2 = sW[(i4 * 4 + 2) * HID + j];
            float w3 = sW[(i4 * 4 + 3) * HID + j];
            #pragma unroll
            for (int n = 0; n < 8; n++) {
                float4 c = c0[n * 16 + i4];
                acc[n] = fmaf(c.x, w0, acc[n]);
                acc[n] = fmaf(c.y, w1, acc[n]);
                acc[n] = fmaf(c.z, w2, acc[n]);
                acc[n] = fmaf(c.w, w3, acc[n]);
            }
        }
        #pragma unroll
        for (int n = 0; n < 8; n++) {
            int node = node0 + g * 8 + n;
            if (node < N_NODES) d_t1[(size_t)node * HID + j] = acc[n];
        }
        __syncthreads();
    }

    long long idx0 = (long long)bid * 256 + tid;
    scatter_range(row, attr4, combined, SPLIT_ITEMS, TOTAL_ITEMS,
                  idx0, (long long)GEMM_BLOCKS * 256);
}

// ---------------------------------------------------------------------------
// K2 (tensor): out = silu(t1 + agg @ W1b) @ W2 + b2   via mma.sync tf32.
// Weights stored in FRAGMENT layout: sW[kt*640 + lane*20 + nt*2 + half]
// so each kt-step needs only 4 LDS.128 for all 8 B-fragment pairs
// (lane stride 20 words -> 8-lane LDS.128 phases are bank-disjoint).
// ---------------------------------------------------------------------------
__global__ void __launch_bounds__(256, 2)
mlp2_mma_kernel(const float* __restrict__ combined,
                const float* __restrict__ W1,
                const float* __restrict__ W2,
                const float* __restrict__ b2,
                float* __restrict__ out) {
    extern __shared__ uint32_t smem_u[];
    uint32_t* sW1 = smem_u;                     // [W_WORDS] frag-layout tf32
    uint32_t* sW2 = sW1 + W_WORDS;              // [W_WORDS]
    uint32_t* sA  = sW2 + W_WORDS;              // [128][A_PAD] agg->h tf32 bits

    int tid  = threadIdx.x;
    int wid  = tid >> 5;
    int lane = tid & 31;
    int g = lane >> 2;
    int t = lane & 3;
    int node0 = blockIdx.x * MT;

    // ---- stage weights in frag layout ----
    // element (k, n): kt=k>>3, kk=k&7, nt=n>>3, gn=n&7; lane'=gn*4+(kk&3),
    // half=kk>>2;  addr = kt*640 + lane'*20 + nt*2 + half
    for (int i = tid; i < HID * HID; i += 256) {
        int k = i >> 6, n = i & 63;
        int kt = k >> 3, kk = k & 7, nt = n >> 3, gn = n & 7;
        int addr = kt * W_KT_BLK + (gn * 4 + (kk & 3)) * WL_STRIDE
                   + nt * 2 + (kk >> 2);
        sW1[addr] = f2tf32(__ldg(W1 + (size_t)(HID + k) * HID + n));
        sW2[addr] = f2tf32(__ldg(W2 + (size_t)k * HID + n));
    }

    // ---- stage agg (combined[:,64:128]) as tf32, row-major [node][k] ----
    const float4* comb4 = (const float4*)combined;
    for (int i = tid; i < MT * 16; i += 256) {      // (node, float4-group)
        int n = i >> 4, q = i & 15;
        int node = node0 + n;
        float4 v = (node < N_NODES)
                     ? __ldg(comb4 + (size_t)node * 32 + 16 + q)
                     : make_float4(0.f, 0.f, 0.f, 0.f);
        uint4 u = make_uint4(f2tf32(v.x), f2tf32(v.y), f2tf32(v.z), f2tf32(v.w));
        *(uint4*)(sA + n * A_PAD + q * 4) = u;
    }
    __syncthreads();

    int m0 = wid * 16;                 // warp's rows within the tile
    int rowA = node0 + m0 + g;         // global node of frag rows (g)
    int rowB = rowA + 8;               // (g+8)
    bool okA = rowA < N_NODES;
    bool okB = rowB < N_NODES;

    const uint4* w1p = (const uint4*)(sW1 + lane * WL_STRIDE);
    const uint4* w2p = (const uint4*)(sW2 + lane * WL_STRIDE);

    // ---- layer 1: D = t1 + agg @ W1b ----
    float d[8][4];
    #pragma unroll
    for (int nt = 0; nt < 8; nt++) {
        float2 vA = make_float2(0.f, 0.f), vB = make_float2(0.f, 0.f);
        if (okA) vA = *(const float2*)(d_t1 + (size_t)rowA * HID + nt * 8 + 2 * t);
        if (okB) vB = *(const float2*)(d_t1 + (size_t)rowB * HID + nt * 8 + 2 * t);
        d[nt][0] = vA.x; d[nt][1] = vA.y; d[nt][2] = vB.x; d[nt][3] = vB.y;
    }

    #pragma unroll
    for (int kt = 0; kt < 8; kt++) {
        const uint32_t* ar0 = sA + (m0 + g)     * A_PAD + kt * 8;
        const uint32_t* ar1 = sA + (m0 + g + 8) * A_PAD + kt * 8;
        uint32_t a0 = ar0[t];
        uint32_t a1 = ar1[t];
        uint32_t a2 = ar0[t + 4];
        uint32_t a3 = ar1[t + 4];
        const uint4* wk = (const uint4*)((const uint32_t*)w1p + kt * W_KT_BLK);
        uint4 q0 = wk[0], q1 = wk[1], q2 = wk[2], q3 = wk[3];
        mma_tf32(d[0][0], d[0][1], d[0][2], d[0][3], a0, a1, a2, a3, q0.x, q0.y);
        mma_tf32(d[1][0], d[1][1], d[1][2], d[1][3], a0, a1, a2, a3, q0.z, q0.w);
        mma_tf32(d[2][0], d[2][1], d[2][2], d[2][3], a0, a1, a2, a3, q1.x, q1.y);
        mma_tf32(d[3][0], d[3][1], d[3][2], d[3][3], a0, a1, a2, a3, q1.z, q1.w);
        mma_tf32(d[4][0], d[4][1], d[4][2], d[4][3], a0, a1, a2, a3, q2.x, q2.y);
        mma_tf32(d[5][0], d[5][1], d[5][2], d[5][3], a0, a1, a2, a3, q2.z, q2.w);
        mma_tf32(d[6][0], d[6][1], d[6][2], d[6][3], a0, a1, a2, a3, q3.x, q3.y);
        mma_tf32(d[7][0], d[7][1], d[7][2], d[7][3], a0, a1, a2, a3, q3.z, q3.w);
    }
    __syncwarp();   // all layer-1 A reads (warp-private rows) done

    // ---- SiLU; store h (tf32) into the warp's own sA rows ----
    #pragma unroll
    for (int nt = 0; nt < 8; nt++) {
        float h0 = __fdividef(d[nt][0], 1.0f + __expf(-d[nt][0]));
        float h1 = __fdividef(d[nt][1], 1.0f + __expf(-d[nt][1]));
        float h2 = __fdividef(d[nt][2], 1.0f + __expf(-d[nt][2]));
        float h3 = __fdividef(d[nt][3], 1.0f + __expf(-d[nt][3]));
        uint32_t* r0 = sA + (m0 + g)     * A_PAD + nt * 8 + 2 * t;
        uint32_t* r1 = sA + (m0 + g + 8) * A_PAD + nt * 8 + 2 * t;
        *(uint2*)r0 = make_uint2(f2tf32(h0), f2tf32(h1));
        *(uint2*)r1 = make_uint2(f2tf32(h2), f2tf32(h3));
    }
    __syncwarp();

    // ---- layer 2: D = b2 + h @ W2 ----
    #pragma unroll
    for (int nt = 0; nt < 8; nt++) {
        float2 bb = *(const float2*)(b2 + nt * 8 + 2 * t);
        d[nt][0] = bb.x; d[nt][1] = bb.y; d[nt][2] = bb.x; d[nt][3] = bb.y;
    }

    #pragma unroll
    for (int kt = 0; kt < 8; kt++) {
        const uint32_t* ar0 = sA + (m0 + g)     * A_PAD + kt * 8;
        const uint32_t* ar1 = sA + (m0 + g + 8) * A_PAD + kt * 8;
        uint32_t a0 = ar0[t];
        uint32_t a1 = ar1[t];
        uint32_t a2 = ar0[t + 4];
        uint32_t a3 = ar1[t + 4];
        const uint4* wk = (const uint4*)((const uint32_t*)w2p + kt * W_KT_BLK);
        uint4 q0 = wk[0], q1 = wk[1], q2 = wk[2], q3 = wk[3];
        mma_tf32(d[0][0], d[0][1], d[0][2], d[0][3], a0, a1, a2, a3, q0.x, q0.y);
        mma_tf32(d[1][0], d[1][1], d[1][2], d[1][3], a0, a1, a2, a3, q0.z, q0.w);
        mma_tf32(d[2][0], d[2][1], d[2][2], d[2][3], a0, a1, a2, a3, q1.x, q1.y);
        mma_tf32(d[3][0], d[3][1], d[3][2], d[3][3], a0, a1, a2, a3, q1.z, q1.w);
        mma_tf32(d[4][0], d[4][1], d[4][2], d[4][3], a0, a1, a2, a3, q2.x, q2.y);
        mma_tf32(d[5][0], d[5][1], d[5][2], d[5][3], a0, a1, a2, a3, q2.z, q2.w);
        mma_tf32(d[6][0], d[6][1], d[6][2], d[6][3], a0, a1, a2, a3, q3.x, q3.y);
        mma_tf32(d[7][0], d[7][1], d[7][2], d[7][3], a0, a1, a2, a3, q3.z, q3.w);
    }

    // ---- write out ----
    #pragma unroll
    for (int nt = 0; nt < 8; nt++) {
        if (okA) {
            *(float2*)(out + (size_t)rowA * HID + nt * 8 + 2 * t)
                = make_float2(d[nt][0], d[nt][1]);
        }
        if (okB) {
            *(float2*)(out + (size_t)rowB * HID + nt * 8 + 2 * t)
                = make_float2(d[nt][2], d[nt][3]);
        }
    }
}

// ---------------------------------------------------------------------------
extern "C" void kernel_launch(void* const* d_in, const int* in_sizes, int n_in,
                              void* d_out, int out_size) {
    const int*   edge_index = (const int*)d_in[0];
    const float* edge_attr  = (const float*)d_in[1];
    const float* x          = (const float*)d_in[2];
    const float* W1         = (const float*)d_in[3];
    const float* b1         = (const float*)d_in[4];
    const float* W2         = (const float*)d_in[5];
    const float* b2         = (const float*)d_in[6];

    float* out      = (float*)d_out;
    float* combined = out + (size_t)N_NODES * HID;

    cudaMemsetAsync(combined, 0, (size_t)N_NODES * CDIM * sizeof(float));

    // K1: scatter + t1 GEMM + x copy
    {
        int smem = (HID * HID) * 4 + NTILE * 16 * 16;
        cudaFuncSetAttribute(scatter_gemm_kernel,
                             cudaFuncAttributeMaxDynamicSharedMemorySize, smem);
        scatter_gemm_kernel<<<TOTAL_BLOCKS, 256, smem>>>(
            edge_index, (const float4*)edge_attr, (const float4*)x,
            W1, b1, combined);
    }

    // K2: tensor-core MLP
    {
        int smem = (2 * W_WORDS + MT * A_PAD) * (int)sizeof(uint32_t);
        cudaFuncSetAttribute(mlp2_mma_kernel,
                             cudaFuncAttributeMaxDynamicSharedMemorySize, smem);
        mlp2_mma_kernel<<<M_BLOCKS, 256, smem>>>(combined, W1, W2, b2, out);
    }
}

// round 12
// speedup vs baseline: 1.0847x; 1.0847x over previous
#include <cuda_runtime.h>
#include <cuda_bf16.h>
#include <cstdint>

#define N_NODES 50000
#define N_EDGES 1250000
#define HID 64
#define CDIM 128
#define NTILE 32                                     // K1 GEMM tile
#define N_TILES ((N_NODES + NTILE - 1) / NTILE)
#define SCAT_BLOCKS 444
#define GEMM_BLOCKS 148
#define TOTAL_BLOCKS (SCAT_BLOCKS + GEMM_BLOCKS)
#define TOTAL_ITEMS (16LL * N_EDGES)
#define SPLIT_ITEMS 17500000LL

#define MT 128                                       // mlp2 nodes per block
#define M_BLOCKS ((N_NODES + MT - 1) / MT)           // 391
#define A_PAD 76    // act row pad (words): conflict-free frag LDS, 16B aligned
#define W_PAD 72    // weight row pad (words): conflict-free B-frag LDS

// scratch: t1 = x @ W1[0:64] + b1  (fp32, computed free inside K1)
__device__ float d_t1[(size_t)N_NODES * HID];

// ---------------------------------------------------------------------------
// helpers
// ---------------------------------------------------------------------------
__device__ __forceinline__ uint32_t f2tf32(float f) {
    uint32_t r; asm("cvt.rna.tf32.f32 %0, %1;" : "=r"(r) : "f"(f)); return r;
}

__device__ __forceinline__ void mma_tf32(float& d0, float& d1, float& d2, float& d3,
                                         uint32_t a0, uint32_t a1, uint32_t a2, uint32_t a3,
                                         uint32_t b0, uint32_t b1) {
    asm("mma.sync.aligned.m16n8k8.row.col.f32.tf32.tf32.f32 "
        "{%0,%1,%2,%3}, {%4,%5,%6,%7}, {%8,%9}, {%0,%1,%2,%3};"
        : "+f"(d0), "+f"(d1), "+f"(d2), "+f"(d3)
        : "r"(a0), "r"(a1), "r"(a2), "r"(a3), "r"(b0), "r"(b1));
}

// ---------------------------------------------------------------------------
// scatter: sequential edge_attr stream + v4 reductions (proven)
// ---------------------------------------------------------------------------
__device__ __forceinline__ void scatter_range(const int* __restrict__ row,
                                              const float4* __restrict__ attr4,
                                              float* __restrict__ combined,
                                              long long beg, long long end,
                                              long long idx0, long long stride) {
    int lane = threadIdx.x & 31;
    int g = (int)((beg + idx0) & 15);
    long long idx = beg + idx0;

    while (idx - lane + 31 < end) {
        int e = (int)(idx >> 4);
        int r;
        if ((lane & 15) == 0) r = __ldg(row + e);
        r = __shfl_sync(0xffffffffu, r, lane & 16);
        float4 v = __ldg(attr4 + idx);
        float* dst = combined + (size_t)r * CDIM + HID + g * 4;
        asm volatile("red.global.add.v4.f32 [%0], {%1, %2, %3, %4};"
                     :: "l"(dst), "f"(v.x), "f"(v.y), "f"(v.z), "f"(v.w)
                     : "memory");
        idx += stride;
    }
    if (idx < end) {
        int e = (int)(idx >> 4);
        int r = __ldg(row + e);
        float4 v = __ldg(attr4 + idx);
        float* dst = combined + (size_t)r * CDIM + HID + g * 4;
        asm volatile("red.global.add.v4.f32 [%0], {%1, %2, %3, %4};"
                     :: "l"(dst), "f"(v.x), "f"(v.y), "f"(v.z), "f"(v.w)
                     : "memory");
    }
}

// ---------------------------------------------------------------------------
// K1: fused scatter + t1-GEMM (+ combined[:,0:64] = x copy)  (proven)
// ---------------------------------------------------------------------------
__global__ void scatter_gemm_kernel(const int* __restrict__ row,
                                    const float4* __restrict__ attr4,
                                    const float4* __restrict__ x4,
                                    const float* __restrict__ W1,
                                    const float* __restrict__ b1,
                                    float* __restrict__ combined) {
    int tid = threadIdx.x;

    if (blockIdx.x < SCAT_BLOCKS) {
        long long idx0 = (long long)blockIdx.x * 256 + tid;
        scatter_range(row, attr4, combined, 0, SPLIT_ITEMS,
                      idx0, (long long)SCAT_BLOCKS * 256);
        return;
    }

    extern __shared__ float4 smem4[];
    float*  sW  = (float*)smem4;
    float4* sx4 = smem4 + (HID * HID) / 4;

    for (int i = tid; i < HID * HID; i += 256) sW[i] = W1[i];
    float bj = __ldg(b1 + (tid & 63));
    __syncthreads();

    int g = tid >> 6;
    int j = tid & 63;
    int bid = blockIdx.x - SCAT_BLOCKS;
    float4* comb4 = (float4*)combined;

    for (int tile = bid; tile < N_TILES; tile += GEMM_BLOCKS) {
        int node0 = tile * NTILE;
        for (int i = tid; i < NTILE * 16; i += 256) {
            int n = node0 + (i >> 4), q = i & 15;
            float4 v = make_float4(0.f, 0.f, 0.f, 0.f);
            if (n < N_NODES) {
                v = __ldg(x4 + (size_t)n * 16 + q);
                comb4[(size_t)n * 32 + q] = v;
            }
            sx4[i] = v;
        }
        __syncthreads();

        float acc[8];
        #pragma unroll
        for (int n = 0; n < 8; n++) acc[n] = bj;

        const float4* c0 = sx4 + g * 8 * 16;
        #pragma unroll 4
        for (int i4 = 0; i4 < 16; i4++) {
            float w0 = sW[(i4 * 4 + 0) * HID + j];
            float w1 = sW[(i4 * 4 + 1) * HID + j];
            float w2 = sW[(i4 * 4 + 2) * HID + j];
            float w3 = sW[(i4 * 4 + 3) * HID + j];
            #pragma unroll
            for (int n = 0; n < 8; n++) {
                float4 c = c0[n * 16 + i4];
                acc[n] = fmaf(c.x, w0, acc[n]);
                acc[n] = fmaf(c.y, w1, acc[n]);
                acc[n] = fmaf(c.z, w2, acc[n]);
                acc[n] = fmaf(c.w, w3, acc[n]);
            }
        }
        #pragma unroll
        for (int n = 0; n < 8; n++) {
            int node = node0 + g * 8 + n;
            if (node < N_NODES) d_t1[(size_t)node * HID + j] = acc[n];
        }
        __syncthreads();
    }

    long long idx0 = (long long)bid * 256 + tid;
    scatter_range(row, attr4, combined, SPLIT_ITEMS, TOTAL_ITEMS,
                  idx0, (long long)GEMM_BLOCKS * 256);
}

// ---------------------------------------------------------------------------
// K2 (tensor): out = silu(t1 + agg @ W1b) @ W2 + b2   via mma.sync tf32.
// R10 formulation (best), with launch_bounds(256,3) -> 3 blocks/SM.
// ---------------------------------------------------------------------------
__global__ void __launch_bounds__(256, 3)
mlp2_mma_kernel(const float* __restrict__ combined,
                const float* __restrict__ W1,
                const float* __restrict__ W2,
                const float* __restrict__ b2,
                float* __restrict__ out) {
    extern __shared__ uint32_t smem_u[];
    uint32_t* sW1 = smem_u;                     // [64][W_PAD] tf32 bits
    uint32_t* sW2 = sW1 + HID * W_PAD;          // [64][W_PAD]
    uint32_t* sA  = sW2 + HID * W_PAD;          // [128][A_PAD] agg->h tf32 bits

    int tid  = threadIdx.x;
    int wid  = tid >> 5;
    int lane = tid & 31;
    int g = lane >> 2;
    int t = lane & 3;
    int node0 = blockIdx.x * MT;

    // ---- stage weights (cvt to tf32), rows 16B-aligned ----
    for (int i = tid; i < HID * 16; i += 256) {     // (k, float4-group)
        int k = i >> 4, q = i & 15;
        float4 v1 = __ldg((const float4*)(W1 + (size_t)(HID + k) * HID) + q);
        float4 v2 = __ldg((const float4*)(W2 + (size_t)k * HID) + q);
        uint4 u1 = make_uint4(f2tf32(v1.x), f2tf32(v1.y), f2tf32(v1.z), f2tf32(v1.w));
        uint4 u2 = make_uint4(f2tf32(v2.x), f2tf32(v2.y), f2tf32(v2.z), f2tf32(v2.w));
        *(uint4*)(sW1 + k * W_PAD + q * 4) = u1;
        *(uint4*)(sW2 + k * W_PAD + q * 4) = u2;
    }

    // ---- stage agg (combined[:,64:128]) as tf32, row-major [node][k] ----
    const float4* comb4 = (const float4*)combined;
    for (int i = tid; i < MT * 16; i += 256) {      // (node, float4-group)
        int n = i >> 4, q = i & 15;
        int node = node0 + n;
        float4 v = (node < N_NODES)
                     ? __ldg(comb4 + (size_t)node * 32 + 16 + q)
                     : make_float4(0.f, 0.f, 0.f, 0.f);
        uint4 u = make_uint4(f2tf32(v.x), f2tf32(v.y), f2tf32(v.z), f2tf32(v.w));
        *(uint4*)(sA + n * A_PAD + q * 4) = u;
    }
    __syncthreads();

    int m0 = wid * 16;                 // warp's rows within the tile
    int rowA = node0 + m0 + g;         // global node of frag rows (g)
    int rowB = rowA + 8;               // (g+8)
    bool okA = rowA < N_NODES;
    bool okB = rowB < N_NODES;

    // ---- layer 1: D = t1 + agg @ W1b ----
    float d[8][4];
    #pragma unroll
    for (int nt = 0; nt < 8; nt++) {
        float2 vA = make_float2(0.f, 0.f), vB = make_float2(0.f, 0.f);
        if (okA) vA = *(const float2*)(d_t1 + (size_t)rowA * HID + nt * 8 + 2 * t);
        if (okB) vB = *(const float2*)(d_t1 + (size_t)rowB * HID + nt * 8 + 2 * t);
        d[nt][0] = vA.x; d[nt][1] = vA.y; d[nt][2] = vB.x; d[nt][3] = vB.y;
    }

    #pragma unroll
    for (int kt = 0; kt < 8; kt++) {
        const uint32_t* ar0 = sA + (m0 + g)     * A_PAD + kt * 8;
        const uint32_t* ar1 = sA + (m0 + g + 8) * A_PAD + kt * 8;
        uint32_t a0 = ar0[t];
        uint32_t a1 = ar1[t];
        uint32_t a2 = ar0[t + 4];
        uint32_t a3 = ar1[t + 4];
        #pragma unroll
        for (int nt = 0; nt < 8; nt++) {
            uint32_t b0 = sW1[(kt * 8 + t)     * W_PAD + nt * 8 + g];
            uint32_t b1 = sW1[(kt * 8 + t + 4) * W_PAD + nt * 8 + g];
            mma_tf32(d[nt][0], d[nt][1], d[nt][2], d[nt][3],
                     a0, a1, a2, a3, b0, b1);
        }
    }
    __syncwarp();   // all layer-1 A reads (warp-private rows) done

    // ---- SiLU; store h (tf32) into the warp's own sA rows ----
    #pragma unroll
    for (int nt = 0; nt < 8; nt++) {
        float h0 = __fdividef(d[nt][0], 1.0f + __expf(-d[nt][0]));
        float h1 = __fdividef(d[nt][1], 1.0f + __expf(-d[nt][1]));
        float h2 = __fdividef(d[nt][2], 1.0f + __expf(-d[nt][2]));
        float h3 = __fdividef(d[nt][3], 1.0f + __expf(-d[nt][3]));
        uint32_t* r0 = sA + (m0 + g)     * A_PAD + nt * 8 + 2 * t;
        uint32_t* r1 = sA + (m0 + g + 8) * A_PAD + nt * 8 + 2 * t;
        *(uint2*)r0 = make_uint2(f2tf32(h0), f2tf32(h1));
        *(uint2*)r1 = make_uint2(f2tf32(h2), f2tf32(h3));
    }
    __syncwarp();

    // ---- layer 2: D = b2 + h @ W2 ----
    #pragma unroll
    for (int nt = 0; nt < 8; nt++) {
        float2 bb = *(const float2*)(b2 + nt * 8 + 2 * t);
        d[nt][0] = bb.x; d[nt][1] = bb.y; d[nt][2] = bb.x; d[nt][3] = bb.y;
    }

    #pragma unroll
    for (int kt = 0; kt < 8; kt++) {
        const uint32_t* ar0 = sA + (m0 + g)     * A_PAD + kt * 8;
        const uint32_t* ar1 = sA + (m0 + g + 8) * A_PAD + kt * 8;
        uint32_t a0 = ar0[t];
        uint32_t a1 = ar1[t];
        uint32_t a2 = ar0[t + 4];
        uint32_t a3 = ar1[t + 4];
        #pragma unroll
        for (int nt = 0; nt < 8; nt++) {
            uint32_t b0 = sW2[(kt * 8 + t)     * W_PAD + nt * 8 + g];
            uint32_t b1 = sW2[(kt * 8 + t + 4) * W_PAD + nt * 8 + g];
            mma_tf32(d[nt][0], d[nt][1], d[nt][2], d[nt][3],
                     a0, a1, a2, a3, b0, b1);
        }
    }

    // ---- write out ----
    #pragma unroll
    for (int nt = 0; nt < 8; nt++) {
        if (okA) {
            *(float2*)(out + (size_t)rowA * HID + nt * 8 + 2 * t)
                = make_float2(d[nt][0], d[nt][1]);
        }
        if (okB) {
            *(float2*)(out + (size_t)rowB * HID + nt * 8 + 2 * t)
                = make_float2(d[nt][2], d[nt][3]);
        }
    }
}

// ---------------------------------------------------------------------------
extern "C" void kernel_launch(void* const* d_in, const int* in_sizes, int n_in,
                              void* d_out, int out_size) {
    const int*   edge_index = (const int*)d_in[0];
    const float* edge_attr  = (const float*)d_in[1];
    const float* x          = (const float*)d_in[2];
    const float* W1         = (const float*)d_in[3];
    const float* b1         = (const float*)d_in[4];
    const float* W2         = (const float*)d_in[5];
    const float* b2         = (const float*)d_in[6];

    float* out      = (float*)d_out;
    float* combined = out + (size_t)N_NODES * HID;

    cudaMemsetAsync(combined, 0, (size_t)N_NODES * CDIM * sizeof(float));

    // K1: scatter + t1 GEMM + x copy
    {
        int smem = (HID * HID) * 4 + NTILE * 16 * 16;
        cudaFuncSetAttribute(scatter_gemm_kernel,
                             cudaFuncAttributeMaxDynamicSharedMemorySize, smem);
        scatter_gemm_kernel<<<TOTAL_BLOCKS, 256, smem>>>(
            edge_index, (const float4*)edge_attr, (const float4*)x,
            W1, b1, combined);
    }

    // K2: tensor-core MLP
    {
        int smem = (2 * HID * W_PAD + MT * A_PAD) * (int)sizeof(uint32_t);
        cudaFuncSetAttribute(mlp2_mma_kernel,
                             cudaFuncAttributeMaxDynamicSharedMemorySize, smem);
        mlp2_mma_kernel<<<M_BLOCKS, 256, smem>>>(combined, W1, W2, b2, out);
    }
}

// round 13
// speedup vs baseline: 1.0968x; 1.0112x over previous
#include <cuda_runtime.h>
#include <cuda_bf16.h>
#include <cstdint>

#define N_NODES 50000
#define N_EDGES 1250000
#define HID 64
#define CDIM 128
#define NTILE 32                                     // K1 GEMM tile
#define N_TILES ((N_NODES + NTILE - 1) / NTILE)
#define SCAT_BLOCKS 444
#define GEMM_BLOCKS 148
#define TOTAL_BLOCKS (SCAT_BLOCKS + GEMM_BLOCKS)
#define TOTAL_ITEMS (16LL * N_EDGES)
#define SPLIT_ITEMS 17500000LL

#define MT 128                                       // mlp2 nodes per block
#define M_BLOCKS ((N_NODES + MT - 1) / MT)           // 391
#define WP2 68      // weight pair-row pad (uint2): conflict-free LDS.64
#define AP2 36      // act pair-row pad (uint2): conflict-free LDS.64

// scratch: t1 = x @ W1[0:64] + b1  (fp32, computed free inside K1)
__device__ float d_t1[(size_t)N_NODES * HID];

// ---------------------------------------------------------------------------
// helpers
// ---------------------------------------------------------------------------
__device__ __forceinline__ uint32_t f2tf32(float f) {
    uint32_t r; asm("cvt.rna.tf32.f32 %0, %1;" : "=r"(r) : "f"(f)); return r;
}

__device__ __forceinline__ void mma_tf32(float& d0, float& d1, float& d2, float& d3,
                                         uint32_t a0, uint32_t a1, uint32_t a2, uint32_t a3,
                                         uint32_t b0, uint32_t b1) {
    asm("mma.sync.aligned.m16n8k8.row.col.f32.tf32.tf32.f32 "
        "{%0,%1,%2,%3}, {%4,%5,%6,%7}, {%8,%9}, {%0,%1,%2,%3};"
        : "+f"(d0), "+f"(d1), "+f"(d2), "+f"(d3)
        : "r"(a0), "r"(a1), "r"(a2), "r"(a3), "r"(b0), "r"(b1));
}

// ---------------------------------------------------------------------------
// scatter: sequential edge_attr stream + v4 reductions (proven)
// ---------------------------------------------------------------------------
__device__ __forceinline__ void scatter_range(const int* __restrict__ row,
                                              const float4* __restrict__ attr4,
                                              float* __restrict__ combined,
                                              long long beg, long long end,
                                              long long idx0, long long stride) {
    int lane = threadIdx.x & 31;
    int g = (int)((beg + idx0) & 15);
    long long idx = beg + idx0;

    while (idx - lane + 31 < end) {
        int e = (int)(idx >> 4);
        int r;
        if ((lane & 15) == 0) r = __ldg(row + e);
        r = __shfl_sync(0xffffffffu, r, lane & 16);
        float4 v = __ldg(attr4 + idx);
        float* dst = combined + (size_t)r * CDIM + HID + g * 4;
        asm volatile("red.global.add.v4.f32 [%0], {%1, %2, %3, %4};"
                     :: "l"(dst), "f"(v.x), "f"(v.y), "f"(v.z), "f"(v.w)
                     : "memory");
        idx += stride;
    }
    if (idx < end) {
        int e = (int)(idx >> 4);
        int r = __ldg(row + e);
        float4 v = __ldg(attr4 + idx);
        float* dst = combined + (size_t)r * CDIM + HID + g * 4;
        asm volatile("red.global.add.v4.f32 [%0], {%1, %2, %3, %4};"
                     :: "l"(dst), "f"(v.x), "f"(v.y), "f"(v.z), "f"(v.w)
                     : "memory");
    }
}

// ---------------------------------------------------------------------------
// K1: fused scatter + t1-GEMM (+ combined[:,0:64] = x copy)  (proven)
// ---------------------------------------------------------------------------
__global__ void scatter_gemm_kernel(const int* __restrict__ row,
                                    const float4* __restrict__ attr4,
                                    const float4* __restrict__ x4,
                                    const float* __restrict__ W1,
                                    const float* __restrict__ b1,
                                    float* __restrict__ combined) {
    int tid = threadIdx.x;

    if (blockIdx.x < SCAT_BLOCKS) {
        long long idx0 = (long long)blockIdx.x * 256 + tid;
        scatter_range(row, attr4, combined, 0, SPLIT_ITEMS,
                      idx0, (long long)SCAT_BLOCKS * 256);
        return;
    }

    extern __shared__ float4 smem4[];
    float*  sW  = (float*)smem4;
    float4* sx4 = smem4 + (HID * HID) / 4;

    for (int i = tid; i < HID * HID; i += 256) sW[i] = W1[i];
    float bj = __ldg(b1 + (tid & 63));
    __syncthreads();

    int g = tid >> 6;
    int j = tid & 63;
    int bid = blockIdx.x - SCAT_BLOCKS;
    float4* comb4 = (float4*)combined;

    for (int tile = bid; tile < N_TILES; tile += GEMM_BLOCKS) {
        int node0 = tile * NTILE;
        for (int i = tid; i < NTILE * 16; i += 256) {
            int n = node0 + (i >> 4), q = i & 15;
            float4 v = make_float4(0.f, 0.f, 0.f, 0.f);
            if (n < N_NODES) {
                v = __ldg(x4 + (size_t)n * 16 + q);
                comb4[(size_t)n * 32 + q] = v;
            }
            sx4[i] = v;
        }
        __syncthreads();

        float acc[8];
        #pragma unroll
        for (int n = 0; n < 8; n++) acc[n] = bj;

        const float4* c0 = sx4 + g * 8 * 16;
        #pragma unroll 4
        for (int i4 = 0; i4 < 16; i4++) {
            float w0 = sW[(i4 * 4 + 0) * HID + j];
            float w1 = sW[(i4 * 4 + 1) * HID + j];
            float w2 = sW[(i4 * 4 + 2) * HID + j];
            float w3 = sW[(i4 * 4 + 3) * HID + j];
            #pragma unroll
            for (int n = 0; n < 8; n++) {
                float4 c = c0[n * 16 + i4];
                acc[n] = fmaf(c.x, w0, acc[n]);
                acc[n] = fmaf(c.y, w1, acc[n]);
                acc[n] = fmaf(c.z, w2, acc[n]);
                acc[n] = fmaf(c.w, w3, acc[n]);
            }
        }
        #pragma unroll
        for (int n = 0; n < 8; n++) {
            int node = node0 + g * 8 + n;
            if (node < N_NODES) d_t1[(size_t)node * HID + j] = acc[n];
        }
        __syncthreads();
    }

    long long idx0 = (long long)bid * 256 + tid;
    scatter_range(row, attr4, combined, SPLIT_ITEMS, TOTAL_ITEMS,
                  idx0, (long long)GEMM_BLOCKS * 256);
}

// ---------------------------------------------------------------------------
// K2 (tensor): out = silu(t1 + agg @ W1b) @ W2 + b2   via mma.sync tf32.
// Pair-interleaved smem: element pairs (k, k+4) stored as one uint2, so each
// A-frag half and each B-frag is a single LDS.64 (hot-loop LDS count halved).
//   sWp[kt*4+t][n]    = { W[kt*8+t][n],    W[kt*8+t+4][n] }      (pad 68)
//   sAp[node][kt*4+t] = { A[node][kt*8+t], A[node][kt*8+t+4] }   (pad 36)
// ---------------------------------------------------------------------------
__global__ void __launch_bounds__(256, 3)
mlp2_mma_kernel(const float* __restrict__ combined,
                const float* __restrict__ W1,
                const float* __restrict__ W2,
                const float* __restrict__ b2,
                float* __restrict__ out) {
    extern __shared__ uint2 smem_p[];
    uint2* sW1p = smem_p;                        // [32][WP2]
    uint2* sW2p = sW1p + 32 * WP2;               // [32][WP2]
    uint2* sAp  = sW2p + 32 * WP2;               // [128][AP2] (agg, then h)

    int tid  = threadIdx.x;
    int wid  = tid >> 5;
    int lane = tid & 31;
    int g = lane >> 2;
    int t = lane & 3;
    int node0 = blockIdx.x * MT;

    // ---- stage weights in (k,k+4)-pair layout ----
    // item = (kp, n-quad): kp = kt*4 + kk2; rows r0 = kt*8+kk2, r1 = r0+4
    for (int i = tid; i < 512; i += 256) {
        int kp = i >> 4, q4 = (i & 15) * 4;
        int kt = kp >> 2, kk2 = kp & 3;
        int r0 = kt * 8 + kk2, r1 = r0 + 4;
        float4 w1a = __ldg((const float4*)(W1 + (size_t)(HID + r0) * HID + q4));
        float4 w1b = __ldg((const float4*)(W1 + (size_t)(HID + r1) * HID + q4));
        float4 w2a = __ldg((const float4*)(W2 + (size_t)r0 * HID + q4));
        float4 w2b = __ldg((const float4*)(W2 + (size_t)r1 * HID + q4));
        uint4* p1 = (uint4*)(sW1p + kp * WP2 + q4);
        uint4* p2 = (uint4*)(sW2p + kp * WP2 + q4);
        p1[0] = make_uint4(f2tf32(w1a.x), f2tf32(w1b.x), f2tf32(w1a.y), f2tf32(w1b.y));
        p1[1] = make_uint4(f2tf32(w1a.z), f2tf32(w1b.z), f2tf32(w1a.w), f2tf32(w1b.w));
        p2[0] = make_uint4(f2tf32(w2a.x), f2tf32(w2b.x), f2tf32(w2a.y), f2tf32(w2b.y));
        p2[1] = make_uint4(f2tf32(w2a.z), f2tf32(w2b.z), f2tf32(w2a.w), f2tf32(w2b.w));
    }

    // ---- stage agg (combined[:,64:128]) in pair layout ----
    // item = (node, k-octet o): k = 8o..8o+7 -> pairs kp = o*4 + 0..3
    const float4* comb4 = (const float4*)combined;
    for (int i = tid; i < MT * 8; i += 256) {
        int n = i >> 3, o = i & 7;
        int node = node0 + n;
        float4 v0 = make_float4(0.f, 0.f, 0.f, 0.f);
        float4 v1 = v0;
        if (node < N_NODES) {
            v0 = __ldg(comb4 + (size_t)node * 32 + 16 + 2 * o);
            v1 = __ldg(comb4 + (size_t)node * 32 + 16 + 2 * o + 1);
        }
        uint4* p = (uint4*)(sAp + n * AP2 + o * 4);
        p[0] = make_uint4(f2tf32(v0.x), f2tf32(v1.x), f2tf32(v0.y), f2tf32(v1.y));
        p[1] = make_uint4(f2tf32(v0.z), f2tf32(v1.z), f2tf32(v0.w), f2tf32(v1.w));
    }

    int m0 = wid * 16;                 // warp's rows within the tile
    int rowA = node0 + m0 + g;         // global node of frag rows (g)
    int rowB = rowA + 8;               // (g+8)
    bool okA = rowA < N_NODES;
    bool okB = rowB < N_NODES;

    // ---- layer 1 accumulators: D = t1 + agg @ W1b ----
    float d[8][4];
    #pragma unroll
    for (int nt = 0; nt < 8; nt++) {
        float2 vA = make_float2(0.f, 0.f), vB = make_float2(0.f, 0.f);
        if (okA) vA = *(const float2*)(d_t1 + (size_t)rowA * HID + nt * 8 + 2 * t);
        if (okB) vB = *(const float2*)(d_t1 + (size_t)rowB * HID + nt * 8 + 2 * t);
        d[nt][0] = vA.x; d[nt][1] = vA.y; d[nt][2] = vB.x; d[nt][3] = vB.y;
    }
    __syncthreads();

    // ---- layer 1 mainloop ----
    #pragma unroll
    for (int kt = 0; kt < 8; kt++) {
        uint2 pA0 = sAp[(m0 + g)     * AP2 + kt * 4 + t];   // {a0, a2}
        uint2 pA1 = sAp[(m0 + g + 8) * AP2 + kt * 4 + t];   // {a1, a3}
        const uint2* wrow = sW1p + (kt * 4 + t) * WP2;
        #pragma unroll
        for (int nt = 0; nt < 8; nt++) {
            uint2 b = wrow[nt * 8 + g];
            mma_tf32(d[nt][0], d[nt][1], d[nt][2], d[nt][3],
                     pA0.x, pA1.x, pA0.y, pA1.y, b.x, b.y);
        }
    }
    __syncwarp();   // warp-private sAp rows: all layer-1 reads done

    // ---- SiLU; store h into warp's own sAp rows, pair layout ----
    // h[row][j]: j = nt*8 + jj, kp = nt*4 + (jj&3), half = jj>>2
    #pragma unroll
    for (int nt = 0; nt < 8; nt++) {
        float h0 = __fdividef(d[nt][0], 1.0f + __expf(-d[nt][0]));  // (g,   2t)
        float h1 = __fdividef(d[nt][1], 1.0f + __expf(-d[nt][1]));  // (g,   2t+1)
        float h2 = __fdividef(d[nt][2], 1.0f + __expf(-d[nt][2]));  // (g+8, 2t)
        float h3 = __fdividef(d[nt][3], 1.0f + __expf(-d[nt][3]));  // (g+8, 2t+1)
        int jj0 = 2 * t, jj1 = 2 * t + 1;
        int w0 = 2 * (nt * 4 + (jj0 & 3)) + (jj0 >> 2);
        int w1 = 2 * (nt * 4 + (jj1 & 3)) + (jj1 >> 2);
        uint32_t* r0 = (uint32_t*)(sAp + (m0 + g)     * AP2);
        uint32_t* r1 = (uint32_t*)(sAp + (m0 + g + 8) * AP2);
        r0[w0] = f2tf32(h0);
        r0[w1] = f2tf32(h1);
        r1[w0] = f2tf32(h2);
        r1[w1] = f2tf32(h3);
    }
    __syncwarp();

    // ---- layer 2: D = b2 + h @ W2 ----
    #pragma unroll
    for (int nt = 0; nt < 8; nt++) {
        float2 bb = *(const float2*)(b2 + nt * 8 + 2 * t);
        d[nt][0] = bb.x; d[nt][1] = bb.y; d[nt][2] = bb.x; d[nt][3] = bb.y;
    }

    #pragma unroll
    for (int kt = 0; kt < 8; kt++) {
        uint2 pA0 = sAp[(m0 + g)     * AP2 + kt * 4 + t];
        uint2 pA1 = sAp[(m0 + g + 8) * AP2 + kt * 4 + t];
        const uint2* wrow = sW2p + (kt * 4 + t) * WP2;
        #pragma unroll
        for (int nt = 0; nt < 8; nt++) {
            uint2 b = wrow[nt * 8 + g];
            mma_tf32(d[nt][0], d[nt][1], d[nt][2], d[nt][3],
                     pA0.x, pA1.x, pA0.y, pA1.y, b.x, b.y);
        }
    }

    // ---- write out ----
    #pragma unroll
    for (int nt = 0; nt < 8; nt++) {
        if (okA) {
            *(float2*)(out + (size_t)rowA * HID + nt * 8 + 2 * t)
                = make_float2(d[nt][0], d[nt][1]);
        }
        if (okB) {
            *(float2*)(out + (size_t)rowB * HID + nt * 8 + 2 * t)
                = make_float2(d[nt][2], d[nt][3]);
        }
    }
}

// ---------------------------------------------------------------------------
extern "C" void kernel_launch(void* const* d_in, const int* in_sizes, int n_in,
                              void* d_out, int out_size) {
    const int*   edge_index = (const int*)d_in[0];
    const float* edge_attr  = (const float*)d_in[1];
    const float* x          = (const float*)d_in[2];
    const float* W1         = (const float*)d_in[3];
    const float* b1         = (const float*)d_in[4];
    const float* W2         = (const float*)d_in[5];
    const float* b2         = (const float*)d_in[6];

    float* out      = (float*)d_out;
    float* combined = out + (size_t)N_NODES * HID;

    cudaMemsetAsync(combined, 0, (size_t)N_NODES * CDIM * sizeof(float));

    // K1: scatter + t1 GEMM + x copy
    {
        int smem = (HID * HID) * 4 + NTILE * 16 * 16;
        cudaFuncSetAttribute(scatter_gemm_kernel,
                             cudaFuncAttributeMaxDynamicSharedMemorySize, smem);
        scatter_gemm_kernel<<<TOTAL_BLOCKS, 256, smem>>>(
            edge_index, (const float4*)edge_attr, (const float4*)x,
            W1, b1, combined);
    }

    // K2: tensor-core MLP
    {
        int smem = (2 * 32 * WP2 + MT * AP2) * (int)sizeof(uint2);
        cudaFuncSetAttribute(mlp2_mma_kernel,
                             cudaFuncAttributeMaxDynamicSharedMemorySize, smem);
        mlp2_mma_kernel<<<M_BLOCKS, 256, smem>>>(combined, W1, W2, b2, out);
    }
}

// round 15
// speedup vs baseline: 1.1073x; 1.0096x over previous
#include <cuda_runtime.h>
#include <cuda_bf16.h>
#include <cuda_fp16.h>
#include <cstdint>

#define N_NODES 50000
#define N_EDGES 1250000
#define HID 64
#define CDIM 128
#define NTILE 32                                     // K1 GEMM tile
#define N_TILES ((N_NODES + NTILE - 1) / NTILE)
#define SCAT_BLOCKS 444
#define GEMM_BLOCKS 148
#define TOTAL_BLOCKS (SCAT_BLOCKS + GEMM_BLOCKS)
#define TOTAL_ITEMS (16LL * N_EDGES)
#define SPLIT_ITEMS 17500000LL

#define MT 128                                       // mlp2 nodes per block
#define M_BLOCKS ((N_NODES + MT - 1) / MT)           // 391
#define APH 20      // act row pad (uint2): 16 slots + pad; (4g+t)%16 per-phase distinct
#define WPH 20      // weight row pad (uint2): same

// scratch: t1 = x @ W1[0:64] + b1  (fp32, computed free inside K1)
__device__ float d_t1[(size_t)N_NODES * HID];

// ---------------------------------------------------------------------------
// helpers
// ---------------------------------------------------------------------------
__device__ __forceinline__ uint32_t h2bits(float lo, float hi) {
    __half2 h = __floats2half2_rn(lo, hi);
    return *(uint32_t*)&h;
}

__device__ __forceinline__ void mma_f16(float& d0, float& d1, float& d2, float& d3,
                                        uint32_t a0, uint32_t a1, uint32_t a2, uint32_t a3,
                                        uint32_t b0, uint32_t b1) {
    asm("mma.sync.aligned.m16n8k16.row.col.f32.f16.f16.f32 "
        "{%0,%1,%2,%3}, {%4,%5,%6,%7}, {%8,%9}, {%0,%1,%2,%3};"
        : "+f"(d0), "+f"(d1), "+f"(d2), "+f"(d3)
        : "r"(a0), "r"(a1), "r"(a2), "r"(a3), "r"(b0), "r"(b1));
}

// ---------------------------------------------------------------------------
// scatter: sequential edge_attr stream + v4 reductions (proven)
// ---------------------------------------------------------------------------
__device__ __forceinline__ void scatter_range(const int* __restrict__ row,
                                              const float4* __restrict__ attr4,
                                              float* __restrict__ combined,
                                              long long beg, long long end,
                                              long long idx0, long long stride) {
    int lane = threadIdx.x & 31;
    int g = (int)((beg + idx0) & 15);
    long long idx = beg + idx0;

    while (idx - lane + 31 < end) {
        int e = (int)(idx >> 4);
        int r;
        if ((lane & 15) == 0) r = __ldg(row + e);
        r = __shfl_sync(0xffffffffu, r, lane & 16);
        float4 v = __ldg(attr4 + idx);
        float* dst = combined + (size_t)r * CDIM + HID + g * 4;
        asm volatile("red.global.add.v4.f32 [%0], {%1, %2, %3, %4};"
                     :: "l"(dst), "f"(v.x), "f"(v.y), "f"(v.z), "f"(v.w)
                     : "memory");
        idx += stride;
    }
    if (idx < end) {
        int e = (int)(idx >> 4);
        int r = __ldg(row + e);
        float4 v = __ldg(attr4 + idx);
        float* dst = combined + (size_t)r * CDIM + HID + g * 4;
        asm volatile("red.global.add.v4.f32 [%0], {%1, %2, %3, %4};"
                     :: "l"(dst), "f"(v.x), "f"(v.y), "f"(v.z), "f"(v.w)
                     : "memory");
    }
}

// ---------------------------------------------------------------------------
// K1: fused scatter + t1-GEMM (+ combined[:,0:64] = x copy)  (proven)
// ---------------------------------------------------------------------------
__global__ void scatter_gemm_kernel(const int* __restrict__ row,
                                    const float4* __restrict__ attr4,
                                    const float4* __restrict__ x4,
                                    const float* __restrict__ W1,
                                    const float* __restrict__ b1,
                                    float* __restrict__ combined) {
    int tid = threadIdx.x;

    if (blockIdx.x < SCAT_BLOCKS) {
        long long idx0 = (long long)blockIdx.x * 256 + tid;
        scatter_range(row, attr4, combined, 0, SPLIT_ITEMS,
                      idx0, (long long)SCAT_BLOCKS * 256);
        return;
    }

    extern __shared__ float4 smem4[];
    float*  sW  = (float*)smem4;
    float4* sx4 = smem4 + (HID * HID) / 4;

    for (int i = tid; i < HID * HID; i += 256) sW[i] = W1[i];
    float bj = __ldg(b1 + (tid & 63));
    __syncthreads();

    int g = tid >> 6;
    int j = tid & 63;
    int bid = blockIdx.x - SCAT_BLOCKS;
    float4* comb4 = (float4*)combined;

    for (int tile = bid; tile < N_TILES; tile += GEMM_BLOCKS) {
        int node0 = tile * NTILE;
        for (int i = tid; i < NTILE * 16; i += 256) {
            int n = node0 + (i >> 4), q = i & 15;
            float4 v = make_float4(0.f, 0.f, 0.f, 0.f);
            if (n < N_NODES) {
                v = __ldg(x4 + (size_t)n * 16 + q);
                comb4[(size_t)n * 32 + q] = v;
            }
            sx4[i] = v;
        }
        __syncthreads();

        float acc[8];
        #pragma unroll
        for (int n = 0; n < 8; n++) acc[n] = bj;

        const float4* c0 = sx4 + g * 8 * 16;
        #pragma unroll 4
        for (int i4 = 0; i4 < 16; i4++) {
            float w0 = sW[(i4 * 4 + 0) * HID + j];
            float w1 = sW[(i4 * 4 + 1) * HID + j];
            float w2 = sW[(i4 * 4 + 2) * HID + j];
            float w3 = sW[(i4 * 4 + 3) * HID + j];
            #pragma unroll
            for (int n = 0; n < 8; n++) {
                float4 c = c0[n * 16 + i4];
                acc[n] = fmaf(c.x, w0, acc[n]);
                acc[n] = fmaf(c.y, w1, acc[n]);
                acc[n] = fmaf(c.z, w2, acc[n]);
                acc[n] = fmaf(c.w, w3, acc[n]);
            }
        }
        #pragma unroll
        for (int n = 0; n < 8; n++) {
            int node = node0 + g * 8 + n;
            if (node < N_NODES) d_t1[(size_t)node * HID + j] = acc[n];
        }
        __syncthreads();
    }

    long long idx0 = (long long)bid * 256 + tid;
    scatter_range(row, attr4, combined, SPLIT_ITEMS, TOTAL_ITEMS,
                  idx0, (long long)GEMM_BLOCKS * 256);
}

// ---------------------------------------------------------------------------
// K2 (tensor): out = silu(t1 + agg @ W1b) @ W2 + b2   via mma.sync fp16 k16.
// fp16 mantissa == tf32 mantissa (10 bits), fp32 accumulate -> same accuracy,
// half the MMAs and fragment loads vs tf32 k8; 40KB smem -> 4 blocks/SM.
// Pair layout (kpair q = fp16x2 of columns/k (2q, 2q+1); 32 kpairs per row,
// 16 uint2 slots): slot kt*4+i = { kpair(kt*8+... ) }:
//   slot s = kt*4 + tt holds { p(kt*8+tt... ) } — concretely:
//   sAp[node][kt*4+t] = { kpair k=kt*16+2t, kpair k=kt*16+8+2t } -> a-frag halves
//   sWp[n][kt*4+t]    = same k pairing for weight column n        -> b-frag
// ---------------------------------------------------------------------------
__global__ void __launch_bounds__(256, 4)
mlp2_mma_kernel(const float* __restrict__ combined,
                const float* __restrict__ W1,
                const float* __restrict__ W2,
                const float* __restrict__ b2,
                float* __restrict__ out) {
    extern __shared__ uint2 smem_p[];
    uint2* sW1p = smem_p;                        // [64][WPH]
    uint2* sW2p = sW1p + HID * WPH;              // [64][WPH]
    uint2* sAp  = sW2p + HID * WPH;              // [128][APH] (agg, then h)

    int tid  = threadIdx.x;
    int wid  = tid >> 5;
    int lane = tid & 31;
    int g = lane >> 2;
    int t = lane & 3;
    int node0 = blockIdx.x * MT;

    // ---- stage weights: item = (kt, tt, n-quad) ----
    // rows k0 = kt*16 + 2*tt (+1), k0+8 (+9)  ->  slot [n][kt*4+tt]
    #pragma unroll
    for (int i = tid; i < 256; i += 256) {       // exactly one item/thread
        int kt = i >> 6, tt = (i >> 4) & 3, n0 = (i & 15) * 4;
        int k0 = kt * 16 + 2 * tt;
        float4 wa = __ldg((const float4*)(W1 + (size_t)(HID + k0)     * HID + n0));
        float4 wb = __ldg((const float4*)(W1 + (size_t)(HID + k0 + 1) * HID + n0));
        float4 wc = __ldg((const float4*)(W1 + (size_t)(HID + k0 + 8) * HID + n0));
        float4 wd = __ldg((const float4*)(W1 + (size_t)(HID + k0 + 9) * HID + n0));
        float4 va = __ldg((const float4*)(W2 + (size_t)k0       * HID + n0));
        float4 vb = __ldg((const float4*)(W2 + (size_t)(k0 + 1) * HID + n0));
        float4 vc = __ldg((const float4*)(W2 + (size_t)(k0 + 8) * HID + n0));
        float4 vd = __ldg((const float4*)(W2 + (size_t)(k0 + 9) * HID + n0));
        int slot = kt * 4 + tt;
        #pragma unroll
        for (int n = 0; n < 4; n++) {
            float a0 = (&wa.x)[n], b0 = (&wb.x)[n], c0 = (&wc.x)[n], d0 = (&wd.x)[n];
            float a2 = (&va.x)[n], b2v = (&vb.x)[n], c2 = (&vc.x)[n], d2 = (&vd.x)[n];
            sW1p[(n0 + n) * WPH + slot] = make_uint2(h2bits(a0, b0), h2bits(c0, d0));
            sW2p[(n0 + n) * WPH + slot] = make_uint2(h2bits(a2, b2v), h2bits(c2, d2));
        }
    }

    // ---- stage agg: item = (node, kt): 16 floats -> 8 kpairs -> 4 uint2 ----
    const float4* comb4 = (const float4*)combined;
    #pragma unroll
    for (int i = tid; i < MT * 4; i += 256) {
        int n = i >> 2, kt = i & 3;
        int node = node0 + n;
        float4 f0 = make_float4(0.f,0.f,0.f,0.f), f1 = f0, f2 = f0, f3 = f0;
        if (node < N_NODES) {
            const float4* src = comb4 + (size_t)node * 32 + 16 + kt * 4;
            f0 = __ldg(src + 0); f1 = __ldg(src + 1);
            f2 = __ldg(src + 2); f3 = __ldg(src + 3);
        }
        // kpairs p0..p7 within this kt; slot (kt*4 + i) = {p_i, p_{i+4}}
        uint32_t p0 = h2bits(f0.x, f0.y), p1 = h2bits(f0.z, f0.w);
        uint32_t p2 = h2bits(f1.x, f1.y), p3 = h2bits(f1.z, f1.w);
        uint32_t p4 = h2bits(f2.x, f2.y), p5 = h2bits(f2.z, f2.w);
        uint32_t p6 = h2bits(f3.x, f3.y), p7 = h2bits(f3.z, f3.w);
        uint4* dst = (uint4*)(sAp + n * APH + kt * 4);
        dst[0] = make_uint4(p0, p4, p1, p5);
        dst[1] = make_uint4(p2, p6, p3, p7);
    }

    int m0 = wid * 16;                 // warp's rows within the tile
    int rowA = node0 + m0 + g;         // frag rows (g)
    int rowB = rowA + 8;               // (g+8)
    bool okA = rowA < N_NODES;
    bool okB = rowB < N_NODES;

    // ---- layer 1 accumulators: D = t1 + agg @ W1b ----
    float d[8][4];
    #pragma unroll
    for (int nt = 0; nt < 8; nt++) {
        float2 vA = make_float2(0.f, 0.f), vB = make_float2(0.f, 0.f);
        if (okA) vA = *(const float2*)(d_t1 + (size_t)rowA * HID + nt * 8 + 2 * t);
        if (okB) vB = *(const float2*)(d_t1 + (size_t)rowB * HID + nt * 8 + 2 * t);
        d[nt][0] = vA.x; d[nt][1] = vA.y; d[nt][2] = vB.x; d[nt][3] = vB.y;
    }
    __syncthreads();

    // ---- layer 1 mainloop (4 kt-steps of K=16) ----
    #pragma unroll
    for (int kt = 0; kt < 4; kt++) {
        uint2 pA0 = sAp[(m0 + g)     * APH + kt * 4 + t];   // {a0, a2}
        uint2 pA1 = sAp[(m0 + g + 8) * APH + kt * 4 + t];   // {a1, a3}
        #pragma unroll
        for (int nt = 0; nt < 8; nt++) {
            uint2 b = sW1p[(nt * 8 + g) * WPH + kt * 4 + t];
            mma_f16(d[nt][0], d[nt][1], d[nt][2], d[nt][3],
                    pA0.x, pA1.x, pA0.y, pA1.y, b.x, b.y);
        }
    }
    __syncwarp();   // warp-private sAp rows: all layer-1 reads done

    // ---- SiLU; store h into warp's own sAp rows ----
    // h cols (j0, j0+1) with j0 = nt*8 + 2t  ->  global kpair q = nt*4 + t;
    // kt_h = q>>3, r = q&7, slot = kt_h*4 + (r&3), half = r>>2;
    // uint32 word index = 2*slot + half  (max 31 < 2*APH = 40)
    #pragma unroll
    for (int nt = 0; nt < 8; nt++) {
        float h0 = __fdividef(d[nt][0], 1.0f + __expf(-d[nt][0]));
        float h1 = __fdividef(d[nt][1], 1.0f + __expf(-d[nt][1]));
        float h2 = __fdividef(d[nt][2], 1.0f + __expf(-d[nt][2]));
        float h3 = __fdividef(d[nt][3], 1.0f + __expf(-d[nt][3]));
        int q = nt * 4 + t;
        int kt_h = q >> 3, r = q & 7;
        int word = 2 * (kt_h * 4 + (r & 3)) + (r >> 2);
        ((uint32_t*)(sAp + (m0 + g)     * APH))[word] = h2bits(h0, h1);
        ((uint32_t*)(sAp + (m0 + g + 8) * APH))[word] = h2bits(h2, h3);
    }
    __syncwarp();

    // ---- layer 2: D = b2 + h @ W2 ----
    #pragma unroll
    for (int nt = 0; nt < 8; nt++) {
        float2 bb = *(const float2*)(b2 + nt * 8 + 2 * t);
        d[nt][0] = bb.x; d[nt][1] = bb.y; d[nt][2] = bb.x; d[nt][3] = bb.y;
    }

    #pragma unroll
    for (int kt = 0; kt < 4; kt++) {
        uint2 pA0 = sAp[(m0 + g)     * APH + kt * 4 + t];
        uint2 pA1 = sAp[(m0 + g + 8) * APH + kt * 4 + t];
        #pragma unroll
        for (int nt = 0; nt < 8; nt++) {
            uint2 b = sW2p[(nt * 8 + g) * WPH + kt * 4 + t];
            mma_f16(d[nt][0], d[nt][1], d[nt][2], d[nt][3],
                    pA0.x, pA1.x, pA0.y, pA1.y, b.x, b.y);
        }
    }

    // ---- write out ----
    #pragma unroll
    for (int nt = 0; nt < 8; nt++) {
        if (okA) {
            *(float2*)(out + (size_t)rowA * HID + nt * 8 + 2 * t)
                = make_float2(d[nt][0], d[nt][1]);
        }
        if (okB) {
            *(float2*)(out + (size_t)rowB * HID + nt * 8 + 2 * t)
                = make_float2(d[nt][2], d[nt][3]);
        }
    }
}

// ---------------------------------------------------------------------------
extern "C" void kernel_launch(void* const* d_in, const int* in_sizes, int n_in,
                              void* d_out, int out_size) {
    const int*   edge_index = (const int*)d_in[0];
    const float* edge_attr  = (const float*)d_in[1];
    const float* x          = (const float*)d_in[2];
    const float* W1         = (const float*)d_in[3];
    const float* b1         = (const float*)d_in[4];
    const float* W2         = (const float*)d_in[5];
    const float* b2         = (const float*)d_in[6];

    float* out      = (float*)d_out;
    float* combined = out + (size_t)N_NODES * HID;

    cudaMemsetAsync(combined, 0, (size_t)N_NODES * CDIM * sizeof(float));

    // K1: scatter + t1 GEMM + x copy
    {
        int smem = (HID * HID) * 4 + NTILE * 16 * 16;
        cudaFuncSetAttribute(scatter_gemm_kernel,
                             cudaFuncAttributeMaxDynamicSharedMemorySize, smem);
        scatter_gemm_kernel<<<TOTAL_BLOCKS, 256, smem>>>(
            edge_index, (const float4*)edge_attr, (const float4*)x,
            W1, b1, combined);
    }

    // K2: tensor-core MLP (fp16 k16)
    {
        int smem = (2 * HID * WPH + MT * APH) * (int)sizeof(uint2);   // 40 KB
        cudaFuncSetAttribute(mlp2_mma_kernel,
                             cudaFuncAttributeMaxDynamicSharedMemorySize, smem);
        mlp2_mma_kernel<<<M_BLOCKS, 256, smem>>>(combined, W1, W2, b2, out);
    }
}